// round 6
// baseline (speedup 1.0000x reference)
#include <cuda_runtime.h>
#include <cuda_fp16.h>
#include <cstdint>

// ============================================================================
// Problem geometry
// ============================================================================
#define TOKENS 8192
#define D_IN   4096
#define D_OUT  4096

// GEMM tiling: block 128x128, BK=128 int8, 8 warps (2x4), warp tile 64x32
#define BM 128
#define BN 128
#define BK 128
#define STAGES 4
#define NIT (D_IN / BK)          // 32 k-iterations

#define TILE_BYTES  (128 * 128)             // 16384 (one 128x128 int8 tile)
#define STAGE_BYTES (3 * TILE_BYTES)        // A_hi + A_lo + B = 49152
#define SMEM_TOTAL  (STAGES * STAGE_BYTES)  // 196608

// int8 staging buffers (device globals: no allocation allowed anywhere)
__device__ __align__(1024) int8_t g_xhi[(size_t)TOKENS * D_IN];
__device__ __align__(1024) int8_t g_xlo[(size_t)TOKENS * D_IN];
__device__ __align__(1024) int8_t g_w8[(size_t)D_OUT * D_IN];

// x fixed-point: q = round(2048*x) = hi*128 + lo  (exact 15-bit representation)
#define XSCALE 2048.0f

// ============================================================================
// PTX helpers (base sm_100: cp.async + ldmatrix + mma.sync IMMA)
// ============================================================================
__device__ __forceinline__ uint32_t smem_to_u32(const void* p) {
    uint32_t a;
    asm("{ .reg .u64 t; cvta.to.shared.u64 t, %1; cvt.u32.u64 %0, t; }"
        : "=r"(a) : "l"(p));
    return a;
}

__device__ __forceinline__ void cp_async16(uint32_t smem, const void* gmem) {
    asm volatile("cp.async.cg.shared.global [%0], [%1], 16;"
                 :: "r"(smem), "l"(gmem) : "memory");
}
#define CP_COMMIT() asm volatile("cp.async.commit_group;" ::: "memory")
#define CP_WAIT(N)  asm volatile("cp.async.wait_group %0;" :: "n"(N) : "memory")

__device__ __forceinline__ void ldsm_x4(uint32_t* r, uint32_t addr) {
    asm volatile("ldmatrix.sync.aligned.m8n8.x4.shared.b16 {%0,%1,%2,%3}, [%4];"
                 : "=r"(r[0]), "=r"(r[1]), "=r"(r[2]), "=r"(r[3]) : "r"(addr));
}

// m16n8k32 s8 x s8 -> s32
__device__ __forceinline__ void imma16832(int* c, const uint32_t* a,
                                          uint32_t b0, uint32_t b1) {
    asm volatile(
        "mma.sync.aligned.m16n8k32.row.col.s32.s8.s8.s32 "
        "{%0,%1,%2,%3}, {%4,%5,%6,%7}, {%8,%9}, {%0,%1,%2,%3};"
        : "+r"(c[0]), "+r"(c[1]), "+r"(c[2]), "+r"(c[3])
        : "r"(a[0]), "r"(a[1]), "r"(a[2]), "r"(a[3]), "r"(b0), "r"(b1));
}

// ============================================================================
// Conversion kernels
//   x fp32 -> (hi, lo) int8 pair:  q = round(2048 x); hi = (q+64)>>7; lo = q-128*hi
//   wq int32 -> int8 (exact, values already in [-128,127])
// ============================================================================
__global__ void __launch_bounds__(256) cvt_x_kernel(const float4* __restrict__ x,
                                                    char4* __restrict__ hi,
                                                    char4* __restrict__ lo, int n4) {
    int i = blockIdx.x * blockDim.x + threadIdx.x;
    if (i < n4) {
        float4 v = x[i];
        int q0 = __float2int_rn(v.x * XSCALE);
        int q1 = __float2int_rn(v.y * XSCALE);
        int q2 = __float2int_rn(v.z * XSCALE);
        int q3 = __float2int_rn(v.w * XSCALE);
        int h0 = (q0 + 64) >> 7, h1 = (q1 + 64) >> 7;
        int h2 = (q2 + 64) >> 7, h3 = (q3 + 64) >> 7;
        hi[i] = make_char4((char)h0, (char)h1, (char)h2, (char)h3);
        lo[i] = make_char4((char)(q0 - (h0 << 7)), (char)(q1 - (h1 << 7)),
                           (char)(q2 - (h2 << 7)), (char)(q3 - (h3 << 7)));
    }
}

__global__ void __launch_bounds__(256) cvt_w_kernel(const int4* __restrict__ w,
                                                    char4* __restrict__ o, int n4) {
    int i = blockIdx.x * blockDim.x + threadIdx.x;
    if (i < n4) {
        int4 v = w[i];
        o[i] = make_char4((char)v.x, (char)v.y, (char)v.z, (char)v.w);
    }
}

// ============================================================================
// Dual-int8 GEMM:
//   acc_hi[m,n] = sum_k hi[m,k]*w8[n,k];  acc_lo likewise (s32, exact)
//   out[m,n] = (acc_hi*128 + acc_lo) * scales[n]/2048 + bias[n]
//   Smem: rows of 128B (8 x 16B chunks), chunk c of row r at (c ^ (r&7))
// ============================================================================
__global__ void __launch_bounds__(256, 1) gemm_kernel(
    const int8_t* __restrict__ Ahi,
    const int8_t* __restrict__ Alo,
    const int8_t* __restrict__ B,
    const float* __restrict__ scales,
    const float* __restrict__ bias,
    float* __restrict__ out) {
    extern __shared__ char smem[];
    const uint32_t sb = smem_to_u32(smem);
    const int tid = threadIdx.x;
    const int wid = tid >> 5;
    const int l = tid & 31;

    const int m0 = blockIdx.y * BM;
    const int n0 = blockIdx.x * BN;
    const int wm0 = (wid >> 2) * 64;     // 0 / 64
    const int wn0 = (wid & 3) * 32;      // 0..96

    // ---- stage loader: 3 x 1024 16B chunks (A_hi, A_lo, B), swizzled ----
    auto load_stage = [&](int it, int st) {
        const int k0 = it * BK;
        const uint32_t s_hi = sb + st * STAGE_BYTES;
        const uint32_t s_lo = s_hi + TILE_BYTES;
        const uint32_t s_b  = s_lo + TILE_BYTES;
#pragma unroll
        for (int j = 0; j < 4; j++) {
            int q = tid + j * 256;
            int r = q >> 3, c = q & 7;
            uint32_t soff = (uint32_t)(r * 128 + ((c ^ (r & 7)) << 4));
            size_t goff = (size_t)(m0 + r) * D_IN + k0 + c * 16;
            cp_async16(s_hi + soff, Ahi + goff);
            cp_async16(s_lo + soff, Alo + goff);
        }
#pragma unroll
        for (int j = 0; j < 4; j++) {
            int q = tid + j * 256;
            int r = q >> 3, c = q & 7;
            uint32_t soff = (uint32_t)(r * 128 + ((c ^ (r & 7)) << 4));
            cp_async16(s_b + soff, B + (size_t)(n0 + r) * D_IN + k0 + c * 16);
        }
        CP_COMMIT();
    };

    // ---- prologue ----
#pragma unroll
    for (int s = 0; s < STAGES - 1; s++) load_stage(s, s);

    int ah_acc[4][4][4], al_acc[4][4][4];
#pragma unroll
    for (int mt = 0; mt < 4; mt++)
#pragma unroll
        for (int nt = 0; nt < 4; nt++)
#pragma unroll
            for (int q = 0; q < 4; q++) {
                ah_acc[mt][nt][q] = 0;
                al_acc[mt][nt][q] = 0;
            }

    // ldmatrix lane addressing: lanes 0-15 -> rows, lanes 16-31 -> +16B k chunk
    const uint32_t a_lane_row = (uint32_t)((wm0 + (l & 15)) * 128);
    const uint32_t b_lane_row = (uint32_t)((wn0 + (l & 15)) * 128);
    const int hi16 = l >> 4;        // 0/1 -> which 16B half of the k32 slice
    const int sw = l & 7;

    // ---- mainloop ----
    for (int it = 0; it < NIT; it++) {
        CP_WAIT(STAGES - 2);
        __syncthreads();

        if (it + STAGES - 1 < NIT) {
            load_stage(it + STAGES - 1, (it + STAGES - 1) % STAGES);
        } else {
            CP_COMMIT();    // constant group count: no tail underflow
        }

        const uint32_t s_hi = sb + (it % STAGES) * STAGE_BYTES;
        const uint32_t s_lo = s_hi + TILE_BYTES;
        const uint32_t s_b  = s_lo + TILE_BYTES;

#pragma unroll
        for (int ks = 0; ks < 4; ks++) {            // 4 k32-slices per stage
            const uint32_t kx = (uint32_t)(((ks * 2 + hi16) ^ sw) << 4);
            uint32_t ah[4][4], al[4][4], bb[2][4];
#pragma unroll
            for (int mt = 0; mt < 4; mt++) {
                ldsm_x4(ah[mt], s_hi + a_lane_row + mt * 2048 + kx);
                ldsm_x4(al[mt], s_lo + a_lane_row + mt * 2048 + kx);
            }
#pragma unroll
            for (int g = 0; g < 2; g++)
                ldsm_x4(bb[g], s_b + b_lane_row + g * 2048 + kx);

#pragma unroll
            for (int mt = 0; mt < 4; mt++)
#pragma unroll
                for (int g = 0; g < 2; g++) {
                    // ldsm_x4 on B: r0=(n lo,k lo) r1=(n hi,k lo)
                    //               r2=(n lo,k hi) r3=(n hi,k hi)
                    imma16832(ah_acc[mt][2 * g + 0], ah[mt], bb[g][0], bb[g][2]);
                    imma16832(ah_acc[mt][2 * g + 1], ah[mt], bb[g][1], bb[g][3]);
                    imma16832(al_acc[mt][2 * g + 0], al[mt], bb[g][0], bb[g][2]);
                    imma16832(al_acc[mt][2 * g + 1], al[mt], bb[g][1], bb[g][3]);
                }
        }
    }

    // ---- epilogue: out = acc_hi*(s/16) + acc_lo*(s/2048) + bias ----
    const int m_base = m0 + wm0 + (l >> 2);
    const int n_base = n0 + wn0 + (l & 3) * 2;
    float sh[4][2], sl[4][2], bv[4][2];
#pragma unroll
    for (int nt = 0; nt < 4; nt++) {
        const int n = n_base + nt * 8;
        float s0 = __ldg(scales + n), s1 = __ldg(scales + n + 1);
        sh[nt][0] = s0 * (1.0f / 16.0f);
        sh[nt][1] = s1 * (1.0f / 16.0f);
        sl[nt][0] = s0 * (1.0f / 2048.0f);
        sl[nt][1] = s1 * (1.0f / 2048.0f);
        bv[nt][0] = __ldg(bias + n);
        bv[nt][1] = __ldg(bias + n + 1);
    }
#pragma unroll
    for (int mt = 0; mt < 4; mt++) {
        const int r0 = m_base + mt * 16;
#pragma unroll
        for (int nt = 0; nt < 4; nt++) {
            const int n = n_base + nt * 8;
            float2 v0, v1;
            v0.x = fmaf((float)ah_acc[mt][nt][0], sh[nt][0],
                        fmaf((float)al_acc[mt][nt][0], sl[nt][0], bv[nt][0]));
            v0.y = fmaf((float)ah_acc[mt][nt][1], sh[nt][1],
                        fmaf((float)al_acc[mt][nt][1], sl[nt][1], bv[nt][1]));
            v1.x = fmaf((float)ah_acc[mt][nt][2], sh[nt][0],
                        fmaf((float)al_acc[mt][nt][2], sl[nt][0], bv[nt][0]));
            v1.y = fmaf((float)ah_acc[mt][nt][3], sh[nt][1],
                        fmaf((float)al_acc[mt][nt][3], sl[nt][1], bv[nt][1]));
            *(float2*)(out + (size_t)r0 * D_OUT + n) = v0;
            *(float2*)(out + (size_t)(r0 + 8) * D_OUT + n) = v1;
        }
    }
}

// ============================================================================
// Host launch
// ============================================================================
extern "C" void kernel_launch(void* const* d_in, const int* in_sizes, int n_in,
                              void* d_out, int out_size) {
    const float* x = (const float*)d_in[0];
    const int* wq = (const int*)d_in[1];
    const float* scales = (const float*)d_in[2];
    const float* bias = (const float*)d_in[3];
    float* out = (float*)d_out;

    void *xhi = nullptr, *xlo = nullptr, *w8 = nullptr;
    cudaGetSymbolAddress(&xhi, g_xhi);
    cudaGetSymbolAddress(&xlo, g_xlo);
    cudaGetSymbolAddress(&w8, g_w8);

    // Stage 1: conversions (x -> exact 15-bit hi/lo int8 pair; wq -> int8 exact)
    {
        int n4x = (TOKENS * D_IN) / 4;
        cvt_x_kernel<<<n4x / 256, 256>>>((const float4*)x, (char4*)xhi,
                                         (char4*)xlo, n4x);
        int n4w = (D_OUT * D_IN) / 4;
        cvt_w_kernel<<<n4w / 256, 256>>>((const int4*)wq, (char4*)w8, n4w);
    }

    // Stage 2: dual-int8 IMMA GEMM + fused dequant epilogue
    static bool attr_set = false;
    if (!attr_set) {
        cudaFuncSetAttribute(gemm_kernel,
                             cudaFuncAttributeMaxDynamicSharedMemorySize,
                             SMEM_TOTAL);
        attr_set = true;
    }
    dim3 grid(D_OUT / BN, TOKENS / BM);   // (32, 64), n fastest for L2 reuse
    gemm_kernel<<<grid, 256, SMEM_TOTAL>>>((const int8_t*)xhi, (const int8_t*)xlo,
                                           (const int8_t*)w8, scales, bias, out);
}

// round 7
// speedup vs baseline: 1.0166x; 1.0166x over previous
#include <cuda_runtime.h>
#include <cuda_fp16.h>
#include <cstdint>

// ============================================================================
// Problem geometry
// ============================================================================
#define TOKENS 8192
#define D_IN   4096
#define D_OUT  4096

// GEMM tiling: block 128x128, BK=128 int8, 16 warps (4x4), warp tile 32x32
#define BM 128
#define BN 128
#define BK 128
#define STAGES 4
#define NTHREADS 512
#define NIT (D_IN / BK)          // 32 k-iterations

#define TILE_BYTES  (128 * 128)             // 16384 (one 128x128 int8 tile)
#define STAGE_BYTES (3 * TILE_BYTES)        // A_hi + A_lo + B = 49152
#define SMEM_TOTAL  (STAGES * STAGE_BYTES)  // 196608

// int8 staging buffers (device globals: no allocation allowed anywhere)
__device__ __align__(1024) int8_t g_xhi[(size_t)TOKENS * D_IN];
__device__ __align__(1024) int8_t g_xlo[(size_t)TOKENS * D_IN];
__device__ __align__(1024) int8_t g_w8[(size_t)D_OUT * D_IN];

// x fixed-point: q = round(2048*x) = hi*128 + lo  (exact 15-bit representation)
#define XSCALE 2048.0f

// ============================================================================
// PTX helpers (base sm_100: cp.async + ldmatrix + mma.sync IMMA)
// ============================================================================
__device__ __forceinline__ uint32_t smem_to_u32(const void* p) {
    uint32_t a;
    asm("{ .reg .u64 t; cvta.to.shared.u64 t, %1; cvt.u32.u64 %0, t; }"
        : "=r"(a) : "l"(p));
    return a;
}

__device__ __forceinline__ void cp_async16(uint32_t smem, const void* gmem) {
    asm volatile("cp.async.cg.shared.global [%0], [%1], 16;"
                 :: "r"(smem), "l"(gmem) : "memory");
}
#define CP_COMMIT() asm volatile("cp.async.commit_group;" ::: "memory")
#define CP_WAIT(N)  asm volatile("cp.async.wait_group %0;" :: "n"(N) : "memory")

__device__ __forceinline__ void ldsm_x4(uint32_t* r, uint32_t addr) {
    asm volatile("ldmatrix.sync.aligned.m8n8.x4.shared.b16 {%0,%1,%2,%3}, [%4];"
                 : "=r"(r[0]), "=r"(r[1]), "=r"(r[2]), "=r"(r[3]) : "r"(addr));
}

// m16n8k32 s8 x s8 -> s32
__device__ __forceinline__ void imma16832(int* c, const uint32_t* a,
                                          uint32_t b0, uint32_t b1) {
    asm volatile(
        "mma.sync.aligned.m16n8k32.row.col.s32.s8.s8.s32 "
        "{%0,%1,%2,%3}, {%4,%5,%6,%7}, {%8,%9}, {%0,%1,%2,%3};"
        : "+r"(c[0]), "+r"(c[1]), "+r"(c[2]), "+r"(c[3])
        : "r"(a[0]), "r"(a[1]), "r"(a[2]), "r"(a[3]), "r"(b0), "r"(b1));
}

// ============================================================================
// Merged conversion kernel
//   blocks [0, NBX):        x fp32 -> (hi, lo) int8 pair (exact 15-bit split)
//   blocks [NBX, NBX+NBW):  wq int32 -> int8 (exact)
// ============================================================================
#define N4X ((TOKENS * D_IN) / 4)   // 8388608
#define N4W ((D_OUT * D_IN) / 4)    // 4194304
#define NBX (N4X / 256)             // 32768
#define NBW (N4W / 256)             // 16384

__global__ void __launch_bounds__(256) cvt_kernel(const float4* __restrict__ x,
                                                  char4* __restrict__ hi,
                                                  char4* __restrict__ lo,
                                                  const int4* __restrict__ w,
                                                  char4* __restrict__ w8) {
    int b = blockIdx.x;
    if (b < NBX) {
        int i = b * 256 + threadIdx.x;
        float4 v = x[i];
        int q0 = __float2int_rn(v.x * XSCALE);
        int q1 = __float2int_rn(v.y * XSCALE);
        int q2 = __float2int_rn(v.z * XSCALE);
        int q3 = __float2int_rn(v.w * XSCALE);
        int h0 = (q0 + 64) >> 7, h1 = (q1 + 64) >> 7;
        int h2 = (q2 + 64) >> 7, h3 = (q3 + 64) >> 7;
        hi[i] = make_char4((char)h0, (char)h1, (char)h2, (char)h3);
        lo[i] = make_char4((char)(q0 - (h0 << 7)), (char)(q1 - (h1 << 7)),
                           (char)(q2 - (h2 << 7)), (char)(q3 - (h3 << 7)));
    } else {
        int i = (b - NBX) * 256 + threadIdx.x;
        int4 v = w[i];
        w8[i] = make_char4((char)v.x, (char)v.y, (char)v.z, (char)v.w);
    }
}

// ============================================================================
// Dual-int8 GEMM, 16 warps (4 warps/SMSP occupancy experiment):
//   acc_hi[m,n] = sum_k hi[m,k]*w8[n,k];  acc_lo likewise (s32, exact)
//   out[m,n] = (acc_hi*128 + acc_lo) * scales[n]/2048 + bias[n]
//   Smem: rows of 128B (8 x 16B chunks), chunk c of row r at (c ^ (r&7))
// ============================================================================
__global__ void __launch_bounds__(NTHREADS, 1) gemm_kernel(
    const int8_t* __restrict__ Ahi,
    const int8_t* __restrict__ Alo,
    const int8_t* __restrict__ B,
    const float* __restrict__ scales,
    const float* __restrict__ bias,
    float* __restrict__ out) {
    extern __shared__ char smem[];
    const uint32_t sb = smem_to_u32(smem);
    const int tid = threadIdx.x;
    const int wid = tid >> 5;
    const int l = tid & 31;

    const int m0 = blockIdx.y * BM;
    const int n0 = blockIdx.x * BN;
    const int wm0 = (wid >> 2) * 32;     // 0..96
    const int wn0 = (wid & 3) * 32;      // 0..96

    // ---- stage loader: 3 x 1024 16B chunks (A_hi, A_lo, B), swizzled ----
    auto load_stage = [&](int it, int st) {
        const int k0 = it * BK;
        const uint32_t s_hi = sb + st * STAGE_BYTES;
        const uint32_t s_lo = s_hi + TILE_BYTES;
        const uint32_t s_b  = s_lo + TILE_BYTES;
#pragma unroll
        for (int j = 0; j < 2; j++) {
            int q = tid + j * NTHREADS;
            int r = q >> 3, c = q & 7;
            uint32_t soff = (uint32_t)(r * 128 + ((c ^ (r & 7)) << 4));
            size_t goff = (size_t)(m0 + r) * D_IN + k0 + c * 16;
            cp_async16(s_hi + soff, Ahi + goff);
            cp_async16(s_lo + soff, Alo + goff);
        }
#pragma unroll
        for (int j = 0; j < 2; j++) {
            int q = tid + j * NTHREADS;
            int r = q >> 3, c = q & 7;
            uint32_t soff = (uint32_t)(r * 128 + ((c ^ (r & 7)) << 4));
            cp_async16(s_b + soff, B + (size_t)(n0 + r) * D_IN + k0 + c * 16);
        }
        CP_COMMIT();
    };

    // ---- prologue ----
#pragma unroll
    for (int s = 0; s < STAGES - 1; s++) load_stage(s, s);

    int ah_acc[2][4][4], al_acc[2][4][4];
#pragma unroll
    for (int mt = 0; mt < 2; mt++)
#pragma unroll
        for (int nt = 0; nt < 4; nt++)
#pragma unroll
            for (int q = 0; q < 4; q++) {
                ah_acc[mt][nt][q] = 0;
                al_acc[mt][nt][q] = 0;
            }

    // ldmatrix lane addressing: lanes 0-15 -> rows, lanes 16-31 -> +16B k chunk
    const uint32_t a_lane_row = (uint32_t)((wm0 + (l & 15)) * 128);
    const uint32_t b_lane_row = (uint32_t)((wn0 + (l & 15)) * 128);
    const int hi16 = l >> 4;        // 0/1 -> which 16B half of the k32 slice
    const int sw = l & 7;

    // ---- mainloop ----
    for (int it = 0; it < NIT; it++) {
        CP_WAIT(STAGES - 2);
        __syncthreads();

        if (it + STAGES - 1 < NIT) {
            load_stage(it + STAGES - 1, (it + STAGES - 1) % STAGES);
        } else {
            CP_COMMIT();    // constant group count: no tail underflow
        }

        const uint32_t s_hi = sb + (it % STAGES) * STAGE_BYTES;
        const uint32_t s_lo = s_hi + TILE_BYTES;
        const uint32_t s_b  = s_lo + TILE_BYTES;

#pragma unroll
        for (int ks = 0; ks < 4; ks++) {            // 4 k32-slices per stage
            const uint32_t kx = (uint32_t)(((ks * 2 + hi16) ^ sw) << 4);
            uint32_t ah[2][4], al[2][4], bb[2][4];
#pragma unroll
            for (int mt = 0; mt < 2; mt++) {
                ldsm_x4(ah[mt], s_hi + a_lane_row + mt * 2048 + kx);
                ldsm_x4(al[mt], s_lo + a_lane_row + mt * 2048 + kx);
            }
#pragma unroll
            for (int g = 0; g < 2; g++)
                ldsm_x4(bb[g], s_b + b_lane_row + g * 2048 + kx);

#pragma unroll
            for (int mt = 0; mt < 2; mt++)
#pragma unroll
                for (int g = 0; g < 2; g++) {
                    // ldsm_x4 on B: r0=(n lo,k lo) r1=(n hi,k lo)
                    //               r2=(n lo,k hi) r3=(n hi,k hi)
                    imma16832(ah_acc[mt][2 * g + 0], ah[mt], bb[g][0], bb[g][2]);
                    imma16832(ah_acc[mt][2 * g + 1], ah[mt], bb[g][1], bb[g][3]);
                    imma16832(al_acc[mt][2 * g + 0], al[mt], bb[g][0], bb[g][2]);
                    imma16832(al_acc[mt][2 * g + 1], al[mt], bb[g][1], bb[g][3]);
                }
        }
    }

    // ---- epilogue: out = acc_hi*(s/16) + acc_lo*(s/2048) + bias ----
    const int m_base = m0 + wm0 + (l >> 2);
    const int n_base = n0 + wn0 + (l & 3) * 2;
    float sh[4][2], sl[4][2], bv[4][2];
#pragma unroll
    for (int nt = 0; nt < 4; nt++) {
        const int n = n_base + nt * 8;
        float s0 = __ldg(scales + n), s1 = __ldg(scales + n + 1);
        sh[nt][0] = s0 * (1.0f / 16.0f);
        sh[nt][1] = s1 * (1.0f / 16.0f);
        sl[nt][0] = s0 * (1.0f / 2048.0f);
        sl[nt][1] = s1 * (1.0f / 2048.0f);
        bv[nt][0] = __ldg(bias + n);
        bv[nt][1] = __ldg(bias + n + 1);
    }
#pragma unroll
    for (int mt = 0; mt < 2; mt++) {
        const int r0 = m_base + mt * 16;
#pragma unroll
        for (int nt = 0; nt < 4; nt++) {
            const int n = n_base + nt * 8;
            float2 v0, v1;
            v0.x = fmaf((float)ah_acc[mt][nt][0], sh[nt][0],
                        fmaf((float)al_acc[mt][nt][0], sl[nt][0], bv[nt][0]));
            v0.y = fmaf((float)ah_acc[mt][nt][1], sh[nt][1],
                        fmaf((float)al_acc[mt][nt][1], sl[nt][1], bv[nt][1]));
            v1.x = fmaf((float)ah_acc[mt][nt][2], sh[nt][0],
                        fmaf((float)al_acc[mt][nt][2], sl[nt][0], bv[nt][0]));
            v1.y = fmaf((float)ah_acc[mt][nt][3], sh[nt][1],
                        fmaf((float)al_acc[mt][nt][3], sl[nt][1], bv[nt][1]));
            *(float2*)(out + (size_t)r0 * D_OUT + n) = v0;
            *(float2*)(out + (size_t)(r0 + 8) * D_OUT + n) = v1;
        }
    }
}

// ============================================================================
// Host launch
// ============================================================================
extern "C" void kernel_launch(void* const* d_in, const int* in_sizes, int n_in,
                              void* d_out, int out_size) {
    const float* x = (const float*)d_in[0];
    const int* wq = (const int*)d_in[1];
    const float* scales = (const float*)d_in[2];
    const float* bias = (const float*)d_in[3];
    float* out = (float*)d_out;

    void *xhi = nullptr, *xlo = nullptr, *w8 = nullptr;
    cudaGetSymbolAddress(&xhi, g_xhi);
    cudaGetSymbolAddress(&xlo, g_xlo);
    cudaGetSymbolAddress(&w8, g_w8);

    // Stage 1: merged conversions (x -> exact hi/lo int8 pair; wq -> int8)
    cvt_kernel<<<NBX + NBW, 256>>>((const float4*)x, (char4*)xhi, (char4*)xlo,
                                   (const int4*)wq, (char4*)w8);

    // Stage 2: dual-int8 IMMA GEMM (16 warps/CTA) + fused dequant epilogue
    static bool attr_set = false;
    if (!attr_set) {
        cudaFuncSetAttribute(gemm_kernel,
                             cudaFuncAttributeMaxDynamicSharedMemorySize,
                             SMEM_TOTAL);
        attr_set = true;
    }
    dim3 grid(D_OUT / BN, TOKENS / BM);   // (32, 64), n fastest for L2 reuse
    gemm_kernel<<<grid, NTHREADS, SMEM_TOTAL>>>((const int8_t*)xhi,
                                                (const int8_t*)xlo,
                                                (const int8_t*)w8,
                                                scales, bias, out);
}

// round 8
// speedup vs baseline: 1.1274x; 1.1090x over previous
#include <cuda_runtime.h>
#include <cuda_fp16.h>
#include <cstdint>

// ============================================================================
// Problem geometry
// ============================================================================
#define TOKENS 8192
#define D_IN   4096
#define D_OUT  4096

// GEMM tiling: block 64x128, BK=128 int8, 8 warps (4m x 2n), warp tile 16x64
// 2 CTAs/SM (register- and smem-sized for exactly that).
#define BM 64
#define BN 128
#define BK 128
#define STAGES 3
#define NTHREADS 256
#define NIT (D_IN / BK)          // 32 k-iterations

#define AH_BYTES   (BM * BK)                 // 8192
#define B_BYTES    (BN * BK)                 // 16384
#define STAGE_BYTES (2 * AH_BYTES + B_BYTES) // 32768
#define SMEM_TOTAL (STAGES * STAGE_BYTES)    // 98304 -> 2 CTAs/SM

// int8 staging buffers (device globals: no allocation allowed anywhere)
__device__ __align__(1024) int8_t g_xhi[(size_t)TOKENS * D_IN];
__device__ __align__(1024) int8_t g_xlo[(size_t)TOKENS * D_IN];
__device__ __align__(1024) int8_t g_w8[(size_t)D_OUT * D_IN];

// x fixed-point: q = round(2048*x) = hi*128 + lo  (exact 15-bit representation)
#define XSCALE 2048.0f

// ============================================================================
// PTX helpers (base sm_100: cp.async + ldmatrix + mma.sync IMMA)
// ============================================================================
__device__ __forceinline__ uint32_t smem_to_u32(const void* p) {
    uint32_t a;
    asm("{ .reg .u64 t; cvta.to.shared.u64 t, %1; cvt.u32.u64 %0, t; }"
        : "=r"(a) : "l"(p));
    return a;
}

__device__ __forceinline__ void cp_async16(uint32_t smem, const void* gmem) {
    asm volatile("cp.async.cg.shared.global [%0], [%1], 16;"
                 :: "r"(smem), "l"(gmem) : "memory");
}
#define CP_COMMIT() asm volatile("cp.async.commit_group;" ::: "memory")
#define CP_WAIT(N)  asm volatile("cp.async.wait_group %0;" :: "n"(N) : "memory")

__device__ __forceinline__ void ldsm_x4(uint32_t* r, uint32_t addr) {
    asm volatile("ldmatrix.sync.aligned.m8n8.x4.shared.b16 {%0,%1,%2,%3}, [%4];"
                 : "=r"(r[0]), "=r"(r[1]), "=r"(r[2]), "=r"(r[3]) : "r"(addr));
}

// m16n8k32 s8 x s8 -> s32
__device__ __forceinline__ void imma16832(int* c, const uint32_t* a,
                                          uint32_t b0, uint32_t b1) {
    asm volatile(
        "mma.sync.aligned.m16n8k32.row.col.s32.s8.s8.s32 "
        "{%0,%1,%2,%3}, {%4,%5,%6,%7}, {%8,%9}, {%0,%1,%2,%3};"
        : "+r"(c[0]), "+r"(c[1]), "+r"(c[2]), "+r"(c[3])
        : "r"(a[0]), "r"(a[1]), "r"(a[2]), "r"(a[3]), "r"(b0), "r"(b1));
}

// ============================================================================
// Merged conversion kernel
//   blocks [0, NBX):        x fp32 -> (hi, lo) int8 pair (exact 15-bit split)
//   blocks [NBX, NBX+NBW):  wq int32 -> int8 (exact)
// ============================================================================
#define N4X ((TOKENS * D_IN) / 4)   // 8388608
#define N4W ((D_OUT * D_IN) / 4)    // 4194304
#define NBX (N4X / 256)             // 32768
#define NBW (N4W / 256)             // 16384

__global__ void __launch_bounds__(256) cvt_kernel(const float4* __restrict__ x,
                                                  char4* __restrict__ hi,
                                                  char4* __restrict__ lo,
                                                  const int4* __restrict__ w,
                                                  char4* __restrict__ w8) {
    int b = blockIdx.x;
    if (b < NBX) {
        int i = b * 256 + threadIdx.x;
        float4 v = x[i];
        int q0 = __float2int_rn(v.x * XSCALE);
        int q1 = __float2int_rn(v.y * XSCALE);
        int q2 = __float2int_rn(v.z * XSCALE);
        int q3 = __float2int_rn(v.w * XSCALE);
        int h0 = (q0 + 64) >> 7, h1 = (q1 + 64) >> 7;
        int h2 = (q2 + 64) >> 7, h3 = (q3 + 64) >> 7;
        hi[i] = make_char4((char)h0, (char)h1, (char)h2, (char)h3);
        lo[i] = make_char4((char)(q0 - (h0 << 7)), (char)(q1 - (h1 << 7)),
                           (char)(q2 - (h2 << 7)), (char)(q3 - (h3 << 7)));
    } else {
        int i = (b - NBX) * 256 + threadIdx.x;
        int4 v = w[i];
        w8[i] = make_char4((char)v.x, (char)v.y, (char)v.z, (char)v.w);
    }
}

// ============================================================================
// Dual-int8 GEMM, 2 CTAs/SM:
//   acc_hi[m,n] = sum_k hi[m,k]*w8[n,k];  acc_lo likewise (s32, exact)
//   out[m,n] = (acc_hi*128 + acc_lo) * scales[n]/2048 + bias[n]
//   Smem: rows of 128B (8 x 16B chunks), chunk c of row r at (c ^ (r&7))
// ============================================================================
__global__ void __launch_bounds__(NTHREADS, 2) gemm_kernel(
    const int8_t* __restrict__ Ahi,
    const int8_t* __restrict__ Alo,
    const int8_t* __restrict__ B,
    const float* __restrict__ scales,
    const float* __restrict__ bias,
    float* __restrict__ out) {
    extern __shared__ char smem[];
    const uint32_t sb = smem_to_u32(smem);
    const int tid = threadIdx.x;
    const int wid = tid >> 5;
    const int l = tid & 31;

    const int m0 = blockIdx.y * BM;
    const int n0 = blockIdx.x * BN;
    const int wm0 = (wid >> 1) * 16;     // 0..48  (4 m-warps of m16)
    const int wn0 = (wid & 1) * 64;      // 0/64   (2 n-warps of n64)

    // ---- stage loader: A_hi 512 + A_lo 512 + B 1024 16B chunks, swizzled ----
    auto load_stage = [&](int it, int st) {
        const int k0 = it * BK;
        const uint32_t s_hi = sb + st * STAGE_BYTES;
        const uint32_t s_lo = s_hi + AH_BYTES;
        const uint32_t s_b  = s_lo + AH_BYTES;
#pragma unroll
        for (int j = 0; j < 2; j++) {   // A rows 0..63 (512 chunks over 256 thr)
            int q = tid + j * NTHREADS;
            int r = q >> 3, c = q & 7;
            uint32_t soff = (uint32_t)(r * 128 + ((c ^ (r & 7)) << 4));
            size_t goff = (size_t)(m0 + r) * D_IN + k0 + c * 16;
            cp_async16(s_hi + soff, Ahi + goff);
            cp_async16(s_lo + soff, Alo + goff);
        }
#pragma unroll
        for (int j = 0; j < 4; j++) {   // B rows 0..127 (1024 chunks)
            int q = tid + j * NTHREADS;
            int r = q >> 3, c = q & 7;
            uint32_t soff = (uint32_t)(r * 128 + ((c ^ (r & 7)) << 4));
            cp_async16(s_b + soff, B + (size_t)(n0 + r) * D_IN + k0 + c * 16);
        }
        CP_COMMIT();
    };

    // ---- prologue: fill STAGES-1 stages ----
#pragma unroll
    for (int s = 0; s < STAGES - 1; s++) load_stage(s, s);

    int ah_acc[8][4], al_acc[8][4];     // m16 x n64 x 2 = 64 regs
#pragma unroll
    for (int nt = 0; nt < 8; nt++)
#pragma unroll
        for (int q = 0; q < 4; q++) {
            ah_acc[nt][q] = 0;
            al_acc[nt][q] = 0;
        }

    // ldmatrix lane addressing: lanes 0-15 -> rows, lanes 16-31 -> +16B k chunk
    const uint32_t a_lane_row = (uint32_t)((wm0 + (l & 15)) * 128);
    const uint32_t b_lane_row = (uint32_t)((wn0 + (l & 15)) * 128);
    const int hi16 = l >> 4;        // 0/1 -> which 16B half of the k32 slice
    const int sw = l & 7;

    // ---- mainloop ----
    for (int it = 0; it < NIT; it++) {
        CP_WAIT(STAGES - 2);
        __syncthreads();

        if (it + STAGES - 1 < NIT) {
            load_stage(it + STAGES - 1, (it + STAGES - 1) % STAGES);
        } else {
            CP_COMMIT();    // constant group count: no tail underflow
        }

        const uint32_t s_hi = sb + (it % STAGES) * STAGE_BYTES;
        const uint32_t s_lo = s_hi + AH_BYTES;
        const uint32_t s_b  = s_lo + AH_BYTES;

#pragma unroll
        for (int ks = 0; ks < 4; ks++) {            // 4 k32-slices per stage
            const uint32_t kx = (uint32_t)(((ks * 2 + hi16) ^ sw) << 4);
            uint32_t ah[4], al[4], bb[4][4];
            ldsm_x4(ah, s_hi + a_lane_row + kx);
            ldsm_x4(al, s_lo + a_lane_row + kx);
#pragma unroll
            for (int g = 0; g < 4; g++)             // 4 x n16
                ldsm_x4(bb[g], s_b + b_lane_row + g * 2048 + kx);

#pragma unroll
            for (int g = 0; g < 4; g++) {
                // ldsm_x4 on B: r0=(n lo,k lo) r1=(n hi,k lo)
                //               r2=(n lo,k hi) r3=(n hi,k hi)
                imma16832(ah_acc[2 * g + 0], ah, bb[g][0], bb[g][2]);
                imma16832(ah_acc[2 * g + 1], ah, bb[g][1], bb[g][3]);
                imma16832(al_acc[2 * g + 0], al, bb[g][0], bb[g][2]);
                imma16832(al_acc[2 * g + 1], al, bb[g][1], bb[g][3]);
            }
        }
    }

    // ---- epilogue: out = acc_hi*(s/16) + acc_lo*(s/2048) + bias ----
    const int m_base = m0 + wm0 + (l >> 2);
    const int n_base = n0 + wn0 + (l & 3) * 2;
#pragma unroll
    for (int nt = 0; nt < 8; nt++) {
        const int n = n_base + nt * 8;
        const float s0 = __ldg(scales + n), s1 = __ldg(scales + n + 1);
        const float sh0 = s0 * (1.0f / 16.0f),   sh1 = s1 * (1.0f / 16.0f);
        const float sl0 = s0 * (1.0f / 2048.0f), sl1 = s1 * (1.0f / 2048.0f);
        const float b0 = __ldg(bias + n), b1 = __ldg(bias + n + 1);
        float2 v0, v1;
        v0.x = fmaf((float)ah_acc[nt][0], sh0,
                    fmaf((float)al_acc[nt][0], sl0, b0));
        v0.y = fmaf((float)ah_acc[nt][1], sh1,
                    fmaf((float)al_acc[nt][1], sl1, b1));
        v1.x = fmaf((float)ah_acc[nt][2], sh0,
                    fmaf((float)al_acc[nt][2], sl0, b0));
        v1.y = fmaf((float)ah_acc[nt][3], sh1,
                    fmaf((float)al_acc[nt][3], sl1, b1));
        *(float2*)(out + (size_t)m_base * D_OUT + n) = v0;
        *(float2*)(out + (size_t)(m_base + 8) * D_OUT + n) = v1;
    }
}

// ============================================================================
// Host launch
// ============================================================================
extern "C" void kernel_launch(void* const* d_in, const int* in_sizes, int n_in,
                              void* d_out, int out_size) {
    const float* x = (const float*)d_in[0];
    const int* wq = (const int*)d_in[1];
    const float* scales = (const float*)d_in[2];
    const float* bias = (const float*)d_in[3];
    float* out = (float*)d_out;

    void *xhi = nullptr, *xlo = nullptr, *w8 = nullptr;
    cudaGetSymbolAddress(&xhi, g_xhi);
    cudaGetSymbolAddress(&xlo, g_xlo);
    cudaGetSymbolAddress(&w8, g_w8);

    // Stage 1: merged conversions (x -> exact hi/lo int8 pair; wq -> int8)
    cvt_kernel<<<NBX + NBW, 256>>>((const float4*)x, (char4*)xhi, (char4*)xlo,
                                   (const int4*)wq, (char4*)w8);

    // Stage 2: dual-int8 IMMA GEMM (2 CTAs/SM) + fused dequant epilogue
    static bool attr_set = false;
    if (!attr_set) {
        cudaFuncSetAttribute(gemm_kernel,
                             cudaFuncAttributeMaxDynamicSharedMemorySize,
                             SMEM_TOTAL);
        attr_set = true;
    }
    dim3 grid(D_OUT / BN, TOKENS / BM);   // (32, 128), n fastest for L2 reuse
    gemm_kernel<<<grid, NTHREADS, SMEM_TOTAL>>>((const int8_t*)xhi,
                                                (const int8_t*)xlo,
                                                (const int8_t*)w8,
                                                scales, bias, out);
}

// round 9
// speedup vs baseline: 1.1392x; 1.0105x over previous
#include <cuda_runtime.h>
#include <cuda_fp16.h>
#include <cstdint>

// ============================================================================
// Problem geometry
// ============================================================================
#define TOKENS 8192
#define D_IN   4096
#define D_OUT  4096

// GEMM tiling: block 64x128, BK=128 int8, 8 warps (4m x 2n), warp tile 16x64
// 2 CTAs/SM (register- and smem-sized for exactly that).
#define BM 64
#define BN 128
#define BK 128
#define STAGES 3
#define NTHREADS 256
#define NIT (D_IN / BK)          // 32 k-iterations

#define AH_BYTES   (BM * BK)                 // 8192
#define B_BYTES    (BN * BK)                 // 16384
#define STAGE_BYTES (2 * AH_BYTES + B_BYTES) // 32768
#define SMEM_TOTAL (STAGES * STAGE_BYTES)    // 98304 -> 2 CTAs/SM

// int8 staging buffers (device globals: no allocation allowed anywhere)
__device__ __align__(1024) int8_t g_xhi[(size_t)TOKENS * D_IN];
__device__ __align__(1024) int8_t g_xlo[(size_t)TOKENS * D_IN];
__device__ __align__(1024) int8_t g_w8[(size_t)D_OUT * D_IN];

// x fixed-point: q = round(2048*x) = hi*128 + lo  (exact 15-bit representation)
#define XSCALE 2048.0f

// ============================================================================
// PTX helpers (base sm_100: cp.async + ldmatrix + mma.sync IMMA)
// ============================================================================
__device__ __forceinline__ uint32_t smem_to_u32(const void* p) {
    uint32_t a;
    asm("{ .reg .u64 t; cvta.to.shared.u64 t, %1; cvt.u32.u64 %0, t; }"
        : "=r"(a) : "l"(p));
    return a;
}

__device__ __forceinline__ void cp_async16(uint32_t smem, const void* gmem) {
    asm volatile("cp.async.cg.shared.global [%0], [%1], 16;"
                 :: "r"(smem), "l"(gmem) : "memory");
}
#define CP_COMMIT() asm volatile("cp.async.commit_group;" ::: "memory")
#define CP_WAIT(N)  asm volatile("cp.async.wait_group %0;" :: "n"(N) : "memory")

__device__ __forceinline__ void ldsm_x4(uint32_t* r, uint32_t addr) {
    asm volatile("ldmatrix.sync.aligned.m8n8.x4.shared.b16 {%0,%1,%2,%3}, [%4];"
                 : "=r"(r[0]), "=r"(r[1]), "=r"(r[2]), "=r"(r[3]) : "r"(addr));
}

// m16n8k32 s8 x s8 -> s32
__device__ __forceinline__ void imma16832(int* c, const uint32_t* a,
                                          uint32_t b0, uint32_t b1) {
    asm volatile(
        "mma.sync.aligned.m16n8k32.row.col.s32.s8.s8.s32 "
        "{%0,%1,%2,%3}, {%4,%5,%6,%7}, {%8,%9}, {%0,%1,%2,%3};"
        : "+r"(c[0]), "+r"(c[1]), "+r"(c[2]), "+r"(c[3])
        : "r"(a[0]), "r"(a[1]), "r"(a[2]), "r"(a[3]), "r"(b0), "r"(b1));
}

// ============================================================================
// Merged conversion kernel
//   blocks [0, NBX):        x fp32 -> (hi, lo) int8 pair (exact 15-bit split)
//   blocks [NBX, NBX+NBW):  wq int32 -> int8 (exact)
// ============================================================================
#define N4X ((TOKENS * D_IN) / 4)   // 8388608
#define N4W ((D_OUT * D_IN) / 4)    // 4194304
#define NBX (N4X / 256)             // 32768
#define NBW (N4W / 256)             // 16384

__global__ void __launch_bounds__(256) cvt_kernel(const float4* __restrict__ x,
                                                  char4* __restrict__ hi,
                                                  char4* __restrict__ lo,
                                                  const int4* __restrict__ w,
                                                  char4* __restrict__ w8) {
    int b = blockIdx.x;
    if (b < NBX) {
        int i = b * 256 + threadIdx.x;
        float4 v = x[i];
        int q0 = __float2int_rn(v.x * XSCALE);
        int q1 = __float2int_rn(v.y * XSCALE);
        int q2 = __float2int_rn(v.z * XSCALE);
        int q3 = __float2int_rn(v.w * XSCALE);
        int h0 = (q0 + 64) >> 7, h1 = (q1 + 64) >> 7;
        int h2 = (q2 + 64) >> 7, h3 = (q3 + 64) >> 7;
        hi[i] = make_char4((char)h0, (char)h1, (char)h2, (char)h3);
        lo[i] = make_char4((char)(q0 - (h0 << 7)), (char)(q1 - (h1 << 7)),
                           (char)(q2 - (h2 << 7)), (char)(q3 - (h3 << 7)));
    } else {
        int i = (b - NBX) * 256 + threadIdx.x;
        int4 v = w[i];
        w8[i] = make_char4((char)v.x, (char)v.y, (char)v.z, (char)v.w);
    }
}

// ============================================================================
// Dual-int8 GEMM, 2 CTAs/SM, cp.async spread across k-slices:
//   acc_hi[m,n] = sum_k hi[m,k]*w8[n,k];  acc_lo likewise (s32, exact)
//   out[m,n] = (acc_hi*128 + acc_lo) * scales[n]/2048 + bias[n]
//   Smem: rows of 128B (8 x 16B chunks), chunk c of row r at (c ^ (r&7))
// ============================================================================
__global__ void __launch_bounds__(NTHREADS, 2) gemm_kernel(
    const int8_t* __restrict__ Ahi,
    const int8_t* __restrict__ Alo,
    const int8_t* __restrict__ B,
    const float* __restrict__ scales,
    const float* __restrict__ bias,
    float* __restrict__ out) {
    extern __shared__ char smem[];
    const uint32_t sb = smem_to_u32(smem);
    const int tid = threadIdx.x;
    const int wid = tid >> 5;
    const int l = tid & 31;

    const int m0 = blockIdx.y * BM;
    const int n0 = blockIdx.x * BN;
    const int wm0 = (wid >> 1) * 16;     // 0..48  (4 m-warps of m16)
    const int wn0 = (wid & 1) * 64;      // 0/64   (2 n-warps of n64)

    // ---- per-thread load geometry (constant): 2 A-rows, 4 B-rows ----
    const int lr = tid >> 3;             // 0..31
    const int lc = tid & 7;              // 16B chunk index
    // smem store offsets (swizzled), constant per thread
    uint32_t sA[2], sB[4];
#pragma unroll
    for (int j = 0; j < 2; j++) {
        int r = lr + 32 * j;
        sA[j] = (uint32_t)(r * 128 + ((lc ^ (r & 7)) << 4));
    }
#pragma unroll
    for (int j = 0; j < 4; j++) {
        int r = lr + 32 * j;
        sB[j] = (uint32_t)(r * 128 + ((lc ^ (r & 7)) << 4));
    }
    // global byte offsets, advanced by BK per loaded stage
    uint32_t oA[2], oB[4];
#pragma unroll
    for (int j = 0; j < 2; j++)
        oA[j] = (uint32_t)((m0 + lr + 32 * j) * D_IN + lc * 16);
#pragma unroll
    for (int j = 0; j < 4; j++)
        oB[j] = (uint32_t)((n0 + lr + 32 * j) * D_IN + lc * 16);

    // ---- prologue: fill STAGES-1 stages (monolithic is fine here) ----
#pragma unroll
    for (int s = 0; s < STAGES - 1; s++) {
        const uint32_t d_hi = sb + s * STAGE_BYTES;
        const uint32_t d_lo = d_hi + AH_BYTES;
        const uint32_t d_b  = d_lo + AH_BYTES;
#pragma unroll
        for (int j = 0; j < 2; j++) {
            cp_async16(d_hi + sA[j], Ahi + oA[j]);
            cp_async16(d_lo + sA[j], Alo + oA[j]);
        }
#pragma unroll
        for (int j = 0; j < 4; j++)
            cp_async16(d_b + sB[j], B + oB[j]);
        CP_COMMIT();
#pragma unroll
        for (int j = 0; j < 2; j++) oA[j] += BK;
#pragma unroll
        for (int j = 0; j < 4; j++) oB[j] += BK;
    }

    int ah_acc[8][4], al_acc[8][4];     // m16 x n64 x 2 = 64 regs
#pragma unroll
    for (int nt = 0; nt < 8; nt++)
#pragma unroll
        for (int q = 0; q < 4; q++) {
            ah_acc[nt][q] = 0;
            al_acc[nt][q] = 0;
        }

    // ldmatrix lane addressing: lanes 0-15 -> rows, lanes 16-31 -> +16B k chunk
    const uint32_t a_lane_row = (uint32_t)((wm0 + (l & 15)) * 128);
    const uint32_t b_lane_row = (uint32_t)((wn0 + (l & 15)) * 128);
    const int hi16 = l >> 4;        // 0/1 -> which 16B half of the k32 slice
    const int sw = l & 7;
    const int rot = wid & 3;        // per-warp slice rotation (de-phases LDSM)

    // ---- mainloop ----
    for (int it = 0; it < NIT; it++) {
        CP_WAIT(STAGES - 2);
        __syncthreads();

        const bool do_load = (it + STAGES - 1 < NIT);
        const uint32_t dst = sb + ((it + STAGES - 1) % STAGES) * STAGE_BYTES;
        const uint32_t d_hi = dst;
        const uint32_t d_lo = dst + AH_BYTES;
        const uint32_t d_b  = d_lo + AH_BYTES;

        const uint32_t s_hi = sb + (it % STAGES) * STAGE_BYTES;
        const uint32_t s_lo = s_hi + AH_BYTES;
        const uint32_t s_b  = s_lo + AH_BYTES;

#pragma unroll
        for (int ks4 = 0; ks4 < 4; ks4++) {     // 4 k32-slices per stage
            const int ks = (ks4 + rot) & 3;     // rotated (s32 adds commute)
            const uint32_t kx = (uint32_t)(((ks * 2 + hi16) ^ sw) << 4);
            uint32_t ah[4], al[4], bb[4][4];
            ldsm_x4(ah, s_hi + a_lane_row + kx);
            ldsm_x4(al, s_lo + a_lane_row + kx);
#pragma unroll
            for (int g = 0; g < 4; g++)         // 4 x n16
                ldsm_x4(bb[g], s_b + b_lane_row + g * 2048 + kx);

            // spread next-stage cp.async issues: 2 per slice, placed in the
            // LDSM->IMMA latency shadow
            if (do_load) {
                if (ks4 == 0) {
                    cp_async16(d_hi + sA[0], Ahi + oA[0]);
                    cp_async16(d_lo + sA[0], Alo + oA[0]);
                } else if (ks4 == 1) {
                    cp_async16(d_hi + sA[1], Ahi + oA[1]);
                    cp_async16(d_lo + sA[1], Alo + oA[1]);
                } else if (ks4 == 2) {
                    cp_async16(d_b + sB[0], B + oB[0]);
                    cp_async16(d_b + sB[1], B + oB[1]);
                } else {
                    cp_async16(d_b + sB[2], B + oB[2]);
                    cp_async16(d_b + sB[3], B + oB[3]);
                }
            }

#pragma unroll
            for (int g = 0; g < 4; g++) {
                // ldsm_x4 on B: r0=(n lo,k lo) r1=(n hi,k lo)
                //               r2=(n lo,k hi) r3=(n hi,k hi)
                imma16832(ah_acc[2 * g + 0], ah, bb[g][0], bb[g][2]);
                imma16832(ah_acc[2 * g + 1], ah, bb[g][1], bb[g][3]);
                imma16832(al_acc[2 * g + 0], al, bb[g][0], bb[g][2]);
                imma16832(al_acc[2 * g + 1], al, bb[g][1], bb[g][3]);
            }
        }

        CP_COMMIT();    // constant one group per iteration: no tail underflow
        if (do_load) {
#pragma unroll
            for (int j = 0; j < 2; j++) oA[j] += BK;
#pragma unroll
            for (int j = 0; j < 4; j++) oB[j] += BK;
        }
    }

    // ---- epilogue: out = acc_hi*(s/16) + acc_lo*(s/2048) + bias ----
    const int m_base = m0 + wm0 + (l >> 2);
    const int n_base = n0 + wn0 + (l & 3) * 2;
#pragma unroll
    for (int nt = 0; nt < 8; nt++) {
        const int n = n_base + nt * 8;
        const float s0 = __ldg(scales + n), s1 = __ldg(scales + n + 1);
        const float sh0 = s0 * (1.0f / 16.0f),   sh1 = s1 * (1.0f / 16.0f);
        const float sl0 = s0 * (1.0f / 2048.0f), sl1 = s1 * (1.0f / 2048.0f);
        const float b0 = __ldg(bias + n), b1 = __ldg(bias + n + 1);
        float2 v0, v1;
        v0.x = fmaf((float)ah_acc[nt][0], sh0,
                    fmaf((float)al_acc[nt][0], sl0, b0));
        v0.y = fmaf((float)ah_acc[nt][1], sh1,
                    fmaf((float)al_acc[nt][1], sl1, b1));
        v1.x = fmaf((float)ah_acc[nt][2], sh0,
                    fmaf((float)al_acc[nt][2], sl0, b0));
        v1.y = fmaf((float)ah_acc[nt][3], sh1,
                    fmaf((float)al_acc[nt][3], sl1, b1));
        *(float2*)(out + (size_t)m_base * D_OUT + n) = v0;
        *(float2*)(out + (size_t)(m_base + 8) * D_OUT + n) = v1;
    }
}

// ============================================================================
// Host launch
// ============================================================================
extern "C" void kernel_launch(void* const* d_in, const int* in_sizes, int n_in,
                              void* d_out, int out_size) {
    const float* x = (const float*)d_in[0];
    const int* wq = (const int*)d_in[1];
    const float* scales = (const float*)d_in[2];
    const float* bias = (const float*)d_in[3];
    float* out = (float*)d_out;

    void *xhi = nullptr, *xlo = nullptr, *w8 = nullptr;
    cudaGetSymbolAddress(&xhi, g_xhi);
    cudaGetSymbolAddress(&xlo, g_xlo);
    cudaGetSymbolAddress(&w8, g_w8);

    // Stage 1: merged conversions (x -> exact hi/lo int8 pair; wq -> int8)
    cvt_kernel<<<NBX + NBW, 256>>>((const float4*)x, (char4*)xhi, (char4*)xlo,
                                   (const int4*)wq, (char4*)w8);

    // Stage 2: dual-int8 IMMA GEMM (2 CTAs/SM) + fused dequant epilogue
    static bool attr_set = false;
    if (!attr_set) {
        cudaFuncSetAttribute(gemm_kernel,
                             cudaFuncAttributeMaxDynamicSharedMemorySize,
                             SMEM_TOTAL);
        attr_set = true;
    }
    dim3 grid(D_OUT / BN, TOKENS / BM);   // (32, 128), n fastest for L2 reuse
    gemm_kernel<<<grid, NTHREADS, SMEM_TOTAL>>>((const int8_t*)xhi,
                                                (const int8_t*)xlo,
                                                (const int8_t*)w8,
                                                scales, bias, out);
}